// round 15
// baseline (speedup 1.0000x reference)
#include <cuda_runtime.h>
#include <cuda_fp16.h>
#include <stdint.h>

// DenseEnergyLoss: fp16 tensor-core GEMMs + fp32 exp epilogue, single fused prep.
// arg = a0v(p) + [v,1,1].[u, a0hi, a0fine] (MMA, fp32 accum)  ~= -0.5*d2*log2e
// out = -0.05 * S / 16384

#define NB   4
#define KC   21
#define HH   128
#define WW   128
#define PTOT 4096
#define TS   256
#define NPT  (PTOT/TS)          // 16
#define NTRI (NPT*(NPT+1)/2)    // 136
#define NBLK (NTRI*NB)          // 544 work items
#define GRID 296                // 148 SMs * 2 resident blocks
#define KP   11

#define LOG2E 1.4426950408889634f
#define SPAD  264

__device__ uint32_t g_sp16[NB][12][PTOT];  // half2 seg*roi k-pairs (row 11 zero)
__device__ uint32_t g_vf  [NB][4][PTOT];   // A-side: (v0,v1)(v2,v3)(v4,1)(1,0)
__device__ uint32_t g_uf  [NB][4][PTOT];   // B-side: (u0,u1)(u2,u3)(u4,a0hi)(a0fine,0)
__device__ float    g_a0v [NB][PTOT];
__device__ float    g_gate[NB][PTOT];
__device__ float    g_part[NBLK];
__device__ int      g_cnt;                 // zero-init; last block resets
__device__ int      g_work;                // zero-init; last block resets

__device__ __forceinline__ float ex2(float x) {
    float y; asm("ex2.approx.f32 %0, %1;" : "=f"(y) : "f"(x)); return y;
}
__device__ __forceinline__ uint32_t h2(float a, float b) {
    __half2 h = __floats2half2_rn(a, b);
    return *(uint32_t*)&h;
}
__device__ __forceinline__ void mma_k16(float d[4],
    uint32_t a0, uint32_t a1, uint32_t a2, uint32_t a3,
    uint32_t b0, uint32_t b1) {
    asm volatile("mma.sync.aligned.m16n8k16.row.col.f32.f16.f16.f32 "
        "{%0,%1,%2,%3}, {%4,%5,%6,%7}, {%8,%9}, {%0,%1,%2,%3};"
        : "+f"(d[0]), "+f"(d[1]), "+f"(d[2]), "+f"(d[3])
        : "r"(a0), "r"(a1), "r"(a2), "r"(a3), "r"(b0), "r"(b1));
}
__device__ __forceinline__ void mma_k8(float d[4],
    uint32_t a0, uint32_t a1, uint32_t b0) {
    asm volatile("mma.sync.aligned.m16n8k8.row.col.f32.f16.f16.f32 "
        "{%0,%1,%2,%3}, {%4,%5}, {%6}, {%0,%1,%2,%3};"
        : "+f"(d[0]), "+f"(d[1]), "+f"(d[2]), "+f"(d[3])
        : "r"(a0), "r"(a1), "r"(b0));
}

// ---------------------------------------------------------------------------
// Fused prep: one thread per (n,p). Downsample all 21 k (coalesced float2
// loads, high MLP), fp32 k-max for gate, roi multiply, fp16 pack, features.
// ---------------------------------------------------------------------------
__global__ void prep_kernel(const float* __restrict__ seg,
                            const float* __restrict__ img,
                            const float* __restrict__ roi,
                            const float* __restrict__ lab) {
    int idx = blockIdx.x * blockDim.x + threadIdx.x;   // NB*PTOT
    int n = idx >> 12;
    int p = idx & (PTOT - 1);
    int y = p >> 6, x = p & 63;
    int yy = 2 * y, xx = 2 * x;

    const float* segn = seg + (size_t)n * KC * HH * WW + (size_t)yy * WW + xx;

    float s[KC];
#pragma unroll
    for (int k = 0; k < KC; k++) {
        const float2* r0 = (const float2*)(segn + (size_t)k * HH * WW);
        const float2* r1 = r0 + (WW / 2);
        float2 a = r0[0], b = r1[0];
        s[k] = 0.25f * (a.x + a.y + b.x + b.y);
    }

    float maxs = s[0];
#pragma unroll
    for (int k = 1; k < KC; k++) maxs = fmaxf(maxs, s[k]);

    float r  = roi[((size_t)n * HH + yy) * WW + xx];
    float lv = lab[((size_t)n * HH + yy) * WW + xx];
    float gate = ((int)lv == 255) ? 1.0f : (r - maxs);
    g_gate[n][p] = fmaxf(gate, 0.0f);

#pragma unroll
    for (int k = 0; k < KC; k++) s[k] *= r;
#pragma unroll
    for (int kp = 0; kp < 10; kp++) g_sp16[n][kp][p] = h2(s[2 * kp], s[2 * kp + 1]);
    g_sp16[n][10][p] = h2(s[20], 0.0f);

    float f[5];
    f[0] = (float)x * (1.0f / 40.0f);
    f[1] = (float)y * (1.0f / 40.0f);
    f[2] = img[(((size_t)(n * 3 + 0)) * HH + yy) * WW + xx] * (1.0f / 15.0f);
    f[3] = img[(((size_t)(n * 3 + 1)) * HH + yy) * WW + xx] * (1.0f / 15.0f);
    f[4] = img[(((size_t)(n * 3 + 2)) * HH + yy) * WW + xx] * (1.0f / 15.0f);

    float sv = 0.0f, su = 0.0f, vr[5], ur[5];
#pragma unroll
    for (int c = 0; c < 5; c++) {
        vr[c] = __half2float(__float2half(f[c]));
        ur[c] = __half2float(__float2half(LOG2E * f[c]));
        sv += vr[c] * vr[c];
        su += ur[c] * ur[c];
    }
    g_a0v[n][p] = -0.5f * LOG2E * sv;
    float a0u = (-0.5f / LOG2E) * su;
    float a0hi_f = __half2float(__float2half_rn(a0u));
    float a0fine = a0u - a0hi_f;        // exact residual

    g_vf[n][0][p] = h2(vr[0], vr[1]);
    g_vf[n][1][p] = h2(vr[2], vr[3]);
    g_vf[n][2][p] = h2(vr[4], 1.0f);
    g_vf[n][3][p] = h2(1.0f, 0.0f);
    g_uf[n][0][p] = h2(ur[0], ur[1]);
    g_uf[n][1][p] = h2(ur[2], ur[3]);
    g_uf[n][2][p] = h2(ur[4], a0hi_f);
    g_uf[n][3][p] = h2(a0fine, 0.0f);
}

// ---------------------------------------------------------------------------
// Phase 2: persistent work-stealing tile-pair kernel. 256 thr, 2 blocks/SM
// (128 regs/thread for deep chunk pipelining), unroll 8.
// ---------------------------------------------------------------------------
__global__ __launch_bounds__(256, 2) void pair_kernel(float* __restrict__ out) {
    __shared__ uint32_t sseg[12][SPAD];
    __shared__ uint32_t sfeat[4][SPAD];
    __shared__ __align__(8) float sg[TS];
    __shared__ float red[8];
    __shared__ int s_idx;
    __shared__ int isLast;

    int t = threadIdx.x;
    int w = t >> 5, lane = t & 31;
    int g = lane >> 2, four = lane & 3;

    sseg[11][t] = 0u;   // row 11 constant zero

    while (true) {
        if (t == 0) s_idx = atomicAdd(&g_work, 1);
        __syncthreads();              // publishes s_idx; guards smem reuse
        int widx = s_idx;
        if (widx >= NBLK) break;

        int n = widx / NTRI;
        int tri = widx - n * NTRI;
        int bp = 0;
        while (tri >= NPT - bp) { tri -= NPT - bp; bp++; }
        int bq = bp + tri;
        float offd = (bp == bq) ? 0.0f : 1.0f;

        int p0 = bp * TS, q0 = bq * TS;

#pragma unroll
        for (int kp = 0; kp < KP; kp++) sseg[kp][t] = g_sp16[n][kp][q0 + t];
#pragma unroll
        for (int c = 0; c < 4; c++) sfeat[c][t] = g_uf[n][c][q0 + t];
        sg[t] = g_gate[n][q0 + t] * offd;
        __syncthreads();

        int prb = p0 + w * 32 + g;

        uint32_t A1[2][2], A2[2][4], A3[2][2];
        float a0p[2][2], gp[2][2];
#pragma unroll
        for (int s = 0; s < 2; s++) {
            int base = prb + s * 16;
            A1[s][0] = g_vf[n][four][base];
            A1[s][1] = g_vf[n][four][base + 8];
            A2[s][0] = g_sp16[n][four][base];
            A2[s][1] = g_sp16[n][four][base + 8];
            A2[s][2] = g_sp16[n][four + 4][base];
            A2[s][3] = g_sp16[n][four + 4][base + 8];
            A3[s][0] = g_sp16[n][8 + four][base];
            A3[s][1] = g_sp16[n][8 + four][base + 8];
            a0p[s][0] = g_a0v[n][base];
            a0p[s][1] = g_a0v[n][base + 8];
            gp[s][0]  = g_gate[n][base];
            gp[s][1]  = g_gate[n][base + 8];
        }

        float acc[4] = {0.f, 0.f, 0.f, 0.f};

#pragma unroll 8
        for (int chunk = 0; chunk < TS / 8; chunk++) {
            int qc = chunk * 8;
            int qb = qc + g;
            uint32_t b1a = sfeat[four][qb];
            uint32_t b2a = sseg[four][qb];
            uint32_t b2b = sseg[four + 4][qb];
            uint32_t b2c = sseg[8 + four][qb];
            int c0 = qc + 2 * four;
            float2 gq = *(const float2*)&sg[c0];

#pragma unroll
            for (int s = 0; s < 2; s++) {
                float d1[4];
                d1[0] = a0p[s][0];
                d1[1] = a0p[s][0];
                d1[2] = a0p[s][1];
                d1[3] = a0p[s][1];
                mma_k8(d1, A1[s][0], A1[s][1], b1a);   // + v.u + a0hi + a0fine

                float d2a[4] = {0.f, 0.f, 0.f, 0.f};
                float d2b[4] = {0.f, 0.f, 0.f, 0.f};
                mma_k16(d2a, A2[s][0], A2[s][1], A2[s][2], A2[s][3], b2a, b2b);
                mma_k8(d2b, A3[s][0], A3[s][1], b2c);

                float w00 = ex2(d1[0]);
                float w01 = ex2(d1[1]);
                float w10 = ex2(d1[2]);
                float w11 = ex2(d1[3]);
                acc[s * 2 + 0] = fmaf(w00 * (d2a[0] + d2b[0]), gp[s][0] + gq.x, acc[s * 2 + 0]);
                acc[s * 2 + 0] = fmaf(w01 * (d2a[1] + d2b[1]), gp[s][0] + gq.y, acc[s * 2 + 0]);
                acc[s * 2 + 1] = fmaf(w10 * (d2a[2] + d2b[2]), gp[s][1] + gq.x, acc[s * 2 + 1]);
                acc[s * 2 + 1] = fmaf(w11 * (d2a[3] + d2b[3]), gp[s][1] + gq.y, acc[s * 2 + 1]);
            }
        }

        float accs = (acc[0] + acc[1]) + (acc[2] + acc[3]);

#pragma unroll
        for (int o = 16; o > 0; o >>= 1)
            accs += __shfl_down_sync(0xffffffffu, accs, o);
        if (lane == 0) red[w] = accs;
        __syncthreads();
        if (t == 0) {
            float s = 0.0f;
#pragma unroll
            for (int i = 0; i < 8; i++) s += red[i];
            g_part[widx] = s;
        }
        // loop-top __syncthreads guards smem restage
    }

    if (t == 0) {
        __threadfence();
        int old = atomicAdd(&g_cnt, 1);
        isLast = (old == GRID - 1);
    }
    __syncthreads();

    if (isLast && t < 32) {
        __threadfence();
        float v = 0.0f;
        for (int i = t; i < NBLK; i += 32) v += g_part[i];
#pragma unroll
        for (int o = 16; o > 0; o >>= 1)
            v += __shfl_down_sync(0xffffffffu, v, o);
        if (t == 0) {
            out[0] = v * (-0.05f / 16384.0f);
            g_cnt = 0;
            g_work = 0;
        }
    }
}

extern "C" void kernel_launch(void* const* d_in, const int* in_sizes, int n_in,
                              void* d_out, int out_size) {
    const float* img = (const float*)d_in[0];
    const float* seg = (const float*)d_in[1];
    const float* roi = (const float*)d_in[2];
    const float* lab = (const float*)d_in[3];
    float* out = (float*)d_out;

    prep_kernel<<<(NB * PTOT) / 128, 128>>>(seg, img, roi, lab);
    pair_kernel<<<GRID, 256>>>(out);
}